// round 1
// baseline (speedup 1.0000x reference)
#include <cuda_runtime.h>

#define DIMC 192
#define RJ   48          // DIM / RED
#define BB   4
#define HH   256
#define WW   256
#define HWSZ (HH * WW)   // 65536
#define EPSV 1e-5f

// Scratch (no device allocation allowed): pooled means and generated weights.
__device__ float g_pooled[BB * DIMC];        // [b*DIM + c]
__device__ float g_wt[BB * DIMC * 4];        // 4 surviving masked taps per (b,c)

// ---------------------------------------------------------------------------
// Kernel 1: global average pool per (b,c). One block per channel plane.
// ---------------------------------------------------------------------------
__global__ void pool_kernel(const float* __restrict__ x) {
    const int bc = blockIdx.x;                       // 0..767
    const float4* p = (const float4*)(x + (size_t)bc * HWSZ);
    const int n4 = HWSZ / 4;                         // 16384
    float s = 0.f;
    for (int i = threadIdx.x; i < n4; i += blockDim.x) {
        float4 v = p[i];
        s += (v.x + v.y) + (v.z + v.w);
    }
    // warp reduce
    #pragma unroll
    for (int o = 16; o > 0; o >>= 1) s += __shfl_down_sync(0xffffffffu, s, o);
    __shared__ float sm[32];
    const int lane = threadIdx.x & 31;
    const int wrp  = threadIdx.x >> 5;
    if (lane == 0) sm[wrp] = s;
    __syncthreads();
    if (wrp == 0) {
        s = (lane < (int)(blockDim.x >> 5)) ? sm[lane] : 0.f;
        #pragma unroll
        for (int o = 16; o > 0; o >>= 1) s += __shfl_down_sync(0xffffffffu, s, o);
        if (lane == 0) g_pooled[bc] = s * (1.0f / (float)HWSZ);
    }
}

// ---------------------------------------------------------------------------
// Kernel 2: dynamic weight generation.
//   t = ReLU(BN(pooled @ w1^T));  wt = t @ w2^T + b2;  keep masked taps k=0..3
// One block per batch sample, 768 threads (= DIM * 4 taps).
// ---------------------------------------------------------------------------
__global__ void wgen_kernel(const float* __restrict__ w1,
                            const float* __restrict__ gamma,
                            const float* __restrict__ beta,
                            const float* __restrict__ rmean,
                            const float* __restrict__ rvar,
                            const float* __restrict__ w2,
                            const float* __restrict__ b2) {
    const int b   = blockIdx.x;
    const int tid = threadIdx.x;
    __shared__ float t[RJ];

    if (tid < RJ) {
        const float* pw = w1 + tid * DIMC;
        const float* pp = g_pooled + b * DIMC;
        float acc = 0.f;
        #pragma unroll 8
        for (int c = 0; c < DIMC; c++) acc = fmaf(pp[c], pw[c], acc);
        acc = gamma[tid] * (acc - rmean[tid]) * rsqrtf(rvar[tid] + EPSV) + beta[tid];
        t[tid] = fmaxf(acc, 0.f);
    }
    __syncthreads();

    // tid -> (channel c, tap k). Mask 'A' keeps (0,0),(0,1),(0,2),(1,0) = k 0..3.
    const int c = tid >> 2;
    const int k = tid & 3;
    const int o = c * 9 + k;                 // index into [DIM*K*K] row of w2/b2
    const float* pw2 = w2 + (size_t)o * RJ;
    float acc = b2[o];
    #pragma unroll
    for (int j = 0; j < RJ; j++) acc = fmaf(t[j], pw2[j], acc);
    g_wt[(b * DIMC + c) * 4 + k] = acc;
}

// ---------------------------------------------------------------------------
// Kernel 3: masked depthwise conv. Active taps:
//   out(y,x) = w0*in(y-1,x-1) + w1*in(y-1,x) + w2*in(y-1,x+1) + w3*in(y,x-1) + bias
// Each thread computes 4 consecutive outputs (one float4). Halos come from
// neighbor lines -> L1 hits. Zero padding at y==0 / x edges.
// ---------------------------------------------------------------------------
__global__ void conv_kernel(const float* __restrict__ x,
                            const float* __restrict__ bias,
                            float* __restrict__ out) {
    const int bc = blockIdx.y;               // 0..767
    const int c  = bc % DIMC;
    const float* w = g_wt + bc * 4;
    const float w0 = w[0], w1 = w[1], w2 = w[2], w3 = w[3];
    const float bs = bias[c];

    const int tid = blockIdx.x * blockDim.x + threadIdx.x;  // 0 .. HW/4-1
    const int xq = tid & (WW / 4 - 1);       // 0..63
    const int y  = tid >> 6;
    const int x0 = xq << 2;

    const float* base = x + (size_t)bc * HWSZ;
    const float* rowc = base + y * WW;

    const float4 bv  = *(const float4*)(rowc + x0);
    const float  bm1 = (x0 > 0) ? rowc[x0 - 1] : 0.f;

    float4 av; float am1, ap4;
    if (y > 0) {
        const float* rowm = rowc - WW;
        av  = *(const float4*)(rowm + x0);
        am1 = (x0 > 0)       ? rowm[x0 - 1] : 0.f;
        ap4 = (x0 + 4 < WW)  ? rowm[x0 + 4] : 0.f;
    } else {
        av = make_float4(0.f, 0.f, 0.f, 0.f); am1 = 0.f; ap4 = 0.f;
    }

    float4 o;
    o.x = fmaf(w0, am1,  fmaf(w1, av.x, fmaf(w2, av.y, fmaf(w3, bm1,  bs))));
    o.y = fmaf(w0, av.x, fmaf(w1, av.y, fmaf(w2, av.z, fmaf(w3, bv.x, bs))));
    o.z = fmaf(w0, av.y, fmaf(w1, av.z, fmaf(w2, av.w, fmaf(w3, bv.y, bs))));
    o.w = fmaf(w0, av.z, fmaf(w1, av.w, fmaf(w2, ap4,  fmaf(w3, bv.z, bs))));

    ((float4*)(out + (size_t)bc * HWSZ))[tid] = o;
}

// ---------------------------------------------------------------------------
extern "C" void kernel_launch(void* const* d_in, const int* in_sizes, int n_in,
                              void* d_out, int out_size) {
    const float* x     = (const float*)d_in[0];
    const float* w1    = (const float*)d_in[1];
    const float* gamma = (const float*)d_in[2];
    const float* beta  = (const float*)d_in[3];
    const float* rmean = (const float*)d_in[4];
    const float* rvar  = (const float*)d_in[5];
    const float* w2    = (const float*)d_in[6];
    const float* b2    = (const float*)d_in[7];
    const float* bias  = (const float*)d_in[8];
    float* out = (float*)d_out;

    pool_kernel<<<BB * DIMC, 256>>>(x);
    wgen_kernel<<<BB, DIMC * 4>>>(w1, gamma, beta, rmean, rvar, w2, b2);

    dim3 grid(HWSZ / 4 / 256, BB * DIMC);
    conv_kernel<<<grid, 256>>>(x, bias, out);
}